// round 12
// baseline (speedup 1.0000x reference)
#include <cuda_runtime.h>
#include <cuda_bf16.h>

#define NN 100000
#define NE 3200000
#define NG 64
#define F  64

// ---- scratch (static device globals; no dynamic allocation) ----
__device__ int   g_cnt[NN];        // in-degree (real edges) per dst
__device__ int   g_cur[NN];        // fill cursor per dst
__device__ int   g_rowptr[NN];     // CSR row start (exclusive scan of g_cnt)
__device__ int   g_bsum[128];      // block sums for scan
__device__ float g_dinv[NN];       // deg^-1/2 (with self loop)
__device__ int   g_col[NE];        // CSR: src node per edge, grouped by dst
__device__ float g_w[NE];          // CSR: dinv[src]*dinv[dst]
__device__ float g_A[(size_t)NN * F];
__device__ float g_B[(size_t)NN * F];
__device__ float g_pool[NG * F];
__device__ int   g_gcnt[NG];

// ---------------- init ----------------
__global__ void k_zero() {
    int i = blockIdx.x * blockDim.x + threadIdx.x;
    if (i < NN) { g_cnt[i] = 0; g_cur[i] = 0; }
    if (i < NG * F) g_pool[i] = 0.f;
    if (i < NG) g_gcnt[i] = 0;
}

// ---------------- degree histogram over dst (edge_index is int32) ----------------
__global__ void k_hist(const int* __restrict__ ei) {
    int stride = gridDim.x * blockDim.x;
    for (int e = blockIdx.x * blockDim.x + threadIdx.x; e < NE; e += stride) {
        int d = ei[NE + e];               // edge_index[1][e]
        atomicAdd(&g_cnt[d], 1);
    }
}

__global__ void k_dinv() {
    int i = blockIdx.x * blockDim.x + threadIdx.x;
    if (i < NN) g_dinv[i] = rsqrtf((float)(g_cnt[i] + 1));  // +1 self loop
}

// ---------------- exclusive scan of g_cnt -> g_rowptr ----------------
__global__ void k_scanA() {
    __shared__ int sh[1024];
    int i = blockIdx.x * 1024 + threadIdx.x;
    int v = (i < NN) ? g_cnt[i] : 0;
    sh[threadIdx.x] = v;
    __syncthreads();
    for (int off = 1; off < 1024; off <<= 1) {
        int t = (threadIdx.x >= off) ? sh[threadIdx.x - off] : 0;
        __syncthreads();
        sh[threadIdx.x] += t;
        __syncthreads();
    }
    if (i < NN) g_rowptr[i] = sh[threadIdx.x] - v;   // exclusive within block
    if (threadIdx.x == 1023) g_bsum[blockIdx.x] = sh[1023];
}

__global__ void k_scanB(int nb) {
    if (blockIdx.x == 0 && threadIdx.x == 0) {
        int run = 0;
        for (int i = 0; i < nb; i++) { int t = g_bsum[i]; g_bsum[i] = run; run += t; }
    }
}

__global__ void k_scanC() {
    int i = blockIdx.x * blockDim.x + threadIdx.x;
    if (i < NN) g_rowptr[i] += g_bsum[i >> 10];
}

// ---------------- CSR fill ----------------
__global__ void k_fill(const int* __restrict__ ei) {
    int stride = gridDim.x * blockDim.x;
    for (int e = blockIdx.x * blockDim.x + threadIdx.x; e < NE; e += stride) {
        int s = ei[e];
        int d = ei[NE + e];
        int pos = g_rowptr[d] + atomicAdd(&g_cur[d], 1);
        g_col[pos] = s;
        g_w[pos]   = g_dinv[s] * g_dinv[d];
    }
}

// ---------------- g_A = x @ W1  (Nx3 @ 3x64) ----------------
__global__ void k_lin1(const float* __restrict__ x, const float* __restrict__ W1) {
    int idx = blockIdx.x * blockDim.x + threadIdx.x;
    if (idx >= NN * F) return;
    int n = idx >> 6, f = idx & 63;
    float x0 = __ldg(&x[n * 3]), x1 = __ldg(&x[n * 3 + 1]), x2 = __ldg(&x[n * 3 + 2]);
    g_A[idx] = x0 * __ldg(&W1[f]) + x1 * __ldg(&W1[64 + f]) + x2 * __ldg(&W1[128 + f]);
}

// ---------------- g_B = relu(conv(g_A) + bias), warp per node ----------------
__global__ void k_conv(const float* __restrict__ bias) {
    int n = blockIdx.x * 8 + (threadIdx.x >> 5);
    int lane = threadIdx.x & 31;
    if (n >= NN) return;
    int r0 = g_rowptr[n];
    int r1 = r0 + g_cnt[n];
    const float2* __restrict__ in2 = (const float2*)g_A;
    float ax = 0.f, ay = 0.f;
#pragma unroll 4
    for (int i = r0; i < r1; i++) {
        int s    = g_col[i];            // same addr across warp -> broadcast LDG
        float wt = g_w[i];
        float2 v = __ldg(&in2[s * 32 + lane]);   // coalesced 256B row
        ax += wt * v.x;
        ay += wt * v.y;
    }
    float dn = g_dinv[n];
    float sw = dn * dn;                 // self-loop weight
    float2 v = __ldg(&in2[n * 32 + lane]);
    ax += sw * v.x;
    ay += sw * v.y;
    ax += __ldg(&bias[lane * 2]);
    ay += __ldg(&bias[lane * 2 + 1]);
    float2 o;
    o.x = fmaxf(ax, 0.f);
    o.y = fmaxf(ay, 0.f);
    ((float2*)g_B)[n * 32 + lane] = o;
}

// ---------------- g_A = g_B @ W2  (64x64), 32 nodes/block ----------------
__global__ void k_gemm(const float* __restrict__ W2) {
    __shared__ float W2s[64 * 64];      // 16 KB, [k*64 + f]
    __shared__ float hs[32 * 68];       // 32 node rows, padded to 68 (bank-safe f4)
    int tid = threadIdx.x;
    int nbase = blockIdx.x * 32;
    for (int i = tid; i < 4096; i += 256) W2s[i] = W2[i];
    for (int i = tid; i < 2048; i += 256) {
        int node = i >> 6, k = i & 63;
        hs[node * 68 + k] = g_B[(size_t)(nbase + node) * 64 + k];
    }
    __syncthreads();
    int f = tid & 63, grp = tid >> 6;   // grp owns 8 nodes
    float acc[8];
#pragma unroll
    for (int i = 0; i < 8; i++) acc[i] = 0.f;
#pragma unroll 4
    for (int k4 = 0; k4 < 64; k4 += 4) {
        float4 hv[8];
#pragma unroll
        for (int i = 0; i < 8; i++)
            hv[i] = *(const float4*)&hs[(grp * 8 + i) * 68 + k4];
#pragma unroll
        for (int j = 0; j < 4; j++) {
            float wk = W2s[(k4 + j) * 64 + f];
#pragma unroll
            for (int i = 0; i < 8; i++) {
                float h = (j == 0) ? hv[i].x : (j == 1) ? hv[i].y : (j == 2) ? hv[i].z : hv[i].w;
                acc[i] += h * wk;
            }
        }
    }
#pragma unroll
    for (int i = 0; i < 8; i++)
        g_A[(size_t)(nbase + grp * 8 + i) * 64 + f] = acc[i];
}

// ---------------- pooled sums + counts (batch is int32) ----------------
__global__ void k_pool(const int* __restrict__ batch) {
    int idx = blockIdx.x * blockDim.x + threadIdx.x;
    if (idx >= NN * F) return;
    int n = idx >> 6, f = idx & 63;
    int b = batch[n];                   // broadcast across the 64 f-threads
    atomicAdd(&g_pool[b * 64 + f], g_B[idx]);
    if (f == 0) atomicAdd(&g_gcnt[b], 1);
}

// ---------------- out[g] = (sum_f pool[g][f]*Wr[f]) / count + br ----------------
__global__ void k_final(const float* __restrict__ Wr, const float* __restrict__ br,
                        float* __restrict__ out) {
    int g = threadIdx.x;
    if (g >= NG) return;
    float s = 0.f;
#pragma unroll
    for (int f = 0; f < 64; f++) s += g_pool[g * 64 + f] * Wr[f];
    out[g] = s / fmaxf((float)g_gcnt[g], 1.f) + br[0];
}

extern "C" void kernel_launch(void* const* d_in, const int* in_sizes, int n_in,
                              void* d_out, int out_size) {
    const float* x     = (const float*)d_in[0];
    const int*   ei    = (const int*)d_in[1];     // int32 (JAX x64 disabled)
    const int*   batch = (const int*)d_in[2];     // int32
    const float* W1    = (const float*)d_in[3];
    const float* b1    = (const float*)d_in[4];
    const float* W2    = (const float*)d_in[5];
    const float* b2    = (const float*)d_in[6];
    const float* Wr    = (const float*)d_in[7];
    const float* br    = (const float*)d_in[8];
    float*       out   = (float*)d_out;

    (void)in_sizes; (void)n_in; (void)out_size;

    const int nb = (NN + 1023) / 1024;  // 98 scan blocks

    k_zero<<<(NN + 255) / 256, 256>>>();
    k_hist<<<4096, 256>>>(ei);
    k_dinv<<<(NN + 255) / 256, 256>>>();
    k_scanA<<<nb, 1024>>>();
    k_scanB<<<1, 32>>>(nb);
    k_scanC<<<(NN + 255) / 256, 256>>>();
    k_fill<<<4096, 256>>>(ei);

    k_lin1<<<(NN * F + 255) / 256, 256>>>(x, W1);   // A = x@W1
    k_conv<<<(NN + 7) / 8, 256>>>(b1);              // B = relu(conv(A)+b1)
    k_gemm<<<NN / 32, 256>>>(W2);                   // A = B@W2   (100000 % 32 == 0)
    k_conv<<<(NN + 7) / 8, 256>>>(b2);              // B = relu(conv(A)+b2)

    k_pool<<<(NN * F + 255) / 256, 256>>>(batch);
    k_final<<<1, 64>>>(Wr, br, out);
}

// round 13
// speedup vs baseline: 1.2803x; 1.2803x over previous
#include <cuda_runtime.h>
#include <cuda_fp16.h>

#define NN 100000
#define NE 3200000
#define NG 64
#define F  64

// ---- scratch (static device globals; no dynamic allocation) ----
__device__ int    g_cnt[NN];          // in-degree (real edges) per dst
__device__ int    g_cur[NN];          // fill cursor per dst
__device__ int    g_rowptr[NN];       // CSR row start (exclusive scan of g_cnt)
__device__ int    g_bsum[128];        // block sums for scan
__device__ float  g_dinv[NN];         // deg^-1/2 (with self loop)
__device__ int2   g_edge[NE];         // CSR: {src, w_bits} packed, grouped by dst
__device__ float  g_c3[(size_t)NN * 3];     // conv(x)  [N,3]
__device__ __half2 g_h[(size_t)NN * 32];    // h = relu(conv(x)@W1+b1)  fp16 [N,64]
__device__ float  g_C[(size_t)NN * F];      // conv(h)  [N,64] fp32
__device__ float  g_pool[NG * F];
__device__ int    g_gcnt[NG];

// ---------------- init ----------------
__global__ void k_zero() {
    int i = blockIdx.x * blockDim.x + threadIdx.x;
    if (i < NN) { g_cnt[i] = 0; g_cur[i] = 0; }
    if (i < NG * F) g_pool[i] = 0.f;
    if (i < NG) g_gcnt[i] = 0;
}

// ---------------- degree histogram over dst ----------------
__global__ void k_hist(const int* __restrict__ ei) {
    int stride = gridDim.x * blockDim.x;
    for (int e = blockIdx.x * blockDim.x + threadIdx.x; e < NE; e += stride)
        atomicAdd(&g_cnt[ei[NE + e]], 1);
}

__global__ void k_dinv() {
    int i = blockIdx.x * blockDim.x + threadIdx.x;
    if (i < NN) g_dinv[i] = rsqrtf((float)(g_cnt[i] + 1));  // +1 self loop
}

__global__ void k_gcnt(const int* __restrict__ batch) {
    int i = blockIdx.x * blockDim.x + threadIdx.x;
    if (i < NN) atomicAdd(&g_gcnt[batch[i]], 1);
}

// ---------------- exclusive scan of g_cnt -> g_rowptr (warp-shuffle) ----------------
__global__ void k_scanA() {
    __shared__ int wsum[32];
    int i = blockIdx.x * 1024 + threadIdx.x;
    int lane = threadIdx.x & 31, warp = threadIdx.x >> 5;
    int v = (i < NN) ? g_cnt[i] : 0;
    int s = v;
#pragma unroll
    for (int off = 1; off < 32; off <<= 1) {
        int t = __shfl_up_sync(0xffffffffu, s, off);
        if (lane >= off) s += t;
    }
    if (lane == 31) wsum[warp] = s;
    __syncthreads();
    if (warp == 0) {
        int w = wsum[lane];
        int ws = w;
#pragma unroll
        for (int off = 1; off < 32; off <<= 1) {
            int t = __shfl_up_sync(0xffffffffu, ws, off);
            if (lane >= off) ws += t;
        }
        wsum[lane] = ws - w;   // exclusive warp offsets
        if (lane == 31) g_bsum[blockIdx.x] = ws;  // block total
    }
    __syncthreads();
    if (i < NN) g_rowptr[i] = s - v + wsum[warp];
}

__global__ void k_scanB(int nb) {
    if (threadIdx.x == 0) {
        int run = 0;
        for (int i = 0; i < nb; i++) { int t = g_bsum[i]; g_bsum[i] = run; run += t; }
    }
}

__global__ void k_scanC() {
    int i = blockIdx.x * blockDim.x + threadIdx.x;
    if (i < NN) g_rowptr[i] += g_bsum[i >> 10];
}

// ---------------- CSR fill: packed {src, weight} ----------------
__global__ void k_fill(const int* __restrict__ ei) {
    int stride = gridDim.x * blockDim.x;
    for (int e = blockIdx.x * blockDim.x + threadIdx.x; e < NE; e += stride) {
        int s = ei[e];
        int d = ei[NE + e];
        float w = g_dinv[s] * g_dinv[d];
        int pos = g_rowptr[d] + atomicAdd(&g_cur[d], 1);
        g_edge[pos] = make_int2(s, __float_as_int(w));
    }
}

// ---------------- conv3: g_c3 = conv(x), warp per node, lanes over edges ----------------
__global__ void k_conv3(const float* __restrict__ x) {
    int n = blockIdx.x * 8 + (threadIdx.x >> 5);
    int lane = threadIdx.x & 31;
    if (n >= NN) return;
    int r0 = g_rowptr[n];
    int r1 = r0 + g_cnt[n];
    float a0 = 0.f, a1 = 0.f, a2 = 0.f;
    for (int i = r0 + lane; i < r1; i += 32) {
        int2 e = __ldg(&g_edge[i]);
        float w = __int_as_float(e.y);
        int s = e.x;
        a0 += w * __ldg(&x[s * 3]);
        a1 += w * __ldg(&x[s * 3 + 1]);
        a2 += w * __ldg(&x[s * 3 + 2]);
    }
#pragma unroll
    for (int off = 16; off > 0; off >>= 1) {
        a0 += __shfl_down_sync(0xffffffffu, a0, off);
        a1 += __shfl_down_sync(0xffffffffu, a1, off);
        a2 += __shfl_down_sync(0xffffffffu, a2, off);
    }
    if (lane == 0) {
        float dn = g_dinv[n], sw = dn * dn;
        g_c3[n * 3]     = a0 + sw * __ldg(&x[n * 3]);
        g_c3[n * 3 + 1] = a1 + sw * __ldg(&x[n * 3 + 1]);
        g_c3[n * 3 + 2] = a2 + sw * __ldg(&x[n * 3 + 2]);
    }
}

// ---------------- h = relu(c3 @ W1 + b1), fp16 out ----------------
__global__ void k_h(const float* __restrict__ W1, const float* __restrict__ b1) {
    int idx = blockIdx.x * blockDim.x + threadIdx.x;
    if (idx >= NN * 32) return;
    int n = idx >> 5, t = idx & 31;
    int f0 = t * 2;
    float c0 = __ldg(&g_c3[n * 3]), c1 = __ldg(&g_c3[n * 3 + 1]), c2 = __ldg(&g_c3[n * 3 + 2]);
    float v0 = __ldg(&b1[f0])     + c0 * __ldg(&W1[f0])     + c1 * __ldg(&W1[64 + f0])     + c2 * __ldg(&W1[128 + f0]);
    float v1 = __ldg(&b1[f0 + 1]) + c0 * __ldg(&W1[f0 + 1]) + c1 * __ldg(&W1[64 + f0 + 1]) + c2 * __ldg(&W1[128 + f0 + 1]);
    v0 = fmaxf(v0, 0.f);
    v1 = fmaxf(v1, 0.f);
    g_h[(size_t)n * 32 + t] = __floats2half2_rn(v0, v1);
}

// ---------------- conv64: g_C = conv(h), warp per node (fp16 gather) ----------------
__global__ void k_conv64() {
    int n = blockIdx.x * 8 + (threadIdx.x >> 5);
    int lane = threadIdx.x & 31;
    if (n >= NN) return;
    int r0 = g_rowptr[n];
    int r1 = r0 + g_cnt[n];
    float ax = 0.f, ay = 0.f;
#pragma unroll 4
    for (int i = r0; i < r1; i++) {
        int2 e = __ldg(&g_edge[i]);          // broadcast 8B
        float w = __int_as_float(e.y);
        float2 v = __half22float2(__ldg(&g_h[(size_t)e.x * 32 + lane]));  // 128B row
        ax += w * v.x;
        ay += w * v.y;
    }
    float dn = g_dinv[n], sw = dn * dn;
    float2 v = __half22float2(__ldg(&g_h[(size_t)n * 32 + lane]));
    ax += sw * v.x;
    ay += sw * v.y;
    ((float2*)g_C)[(size_t)n * 32 + lane] = make_float2(ax, ay);
}

// ---------------- h2 = relu(g_C @ W2 + b2), fused pooling ----------------
__global__ void k_g2p(const float* __restrict__ W2, const float* __restrict__ b2,
                      const int* __restrict__ batch) {
    __shared__ float W2s[64 * 64];          // [k*64 + f]
    __shared__ float hs[32 * 68];           // 32 node rows, padded
    __shared__ float red[4 * 64];           // grp partial sums per feature
    int tid = threadIdx.x;
    int nbase = blockIdx.x * 32;
    for (int i = tid; i < 4096; i += 256) W2s[i] = W2[i];
    for (int i = tid; i < 2048; i += 256) {
        int node = i >> 6, k = i & 63;
        hs[node * 68 + k] = g_C[(size_t)(nbase + node) * 64 + k];
    }
    __syncthreads();
    int f = tid & 63, grp = tid >> 6;       // grp owns 8 nodes
    float bf = __ldg(&b2[f]);
    float acc[8];
#pragma unroll
    for (int i = 0; i < 8; i++) acc[i] = bf;
#pragma unroll 4
    for (int k4 = 0; k4 < 64; k4 += 4) {
        float4 hv[8];
#pragma unroll
        for (int i = 0; i < 8; i++)
            hv[i] = *(const float4*)&hs[(grp * 8 + i) * 68 + k4];
#pragma unroll
        for (int j = 0; j < 4; j++) {
            float wk = W2s[(k4 + j) * 64 + f];
#pragma unroll
            for (int i = 0; i < 8; i++) {
                float h = (j == 0) ? hv[i].x : (j == 1) ? hv[i].y : (j == 2) ? hv[i].z : hv[i].w;
                acc[i] += h * wk;
            }
        }
    }
    int b_lo = __ldg(&batch[nbase]);
    int b_hi = __ldg(&batch[nbase + 31]);
    if (b_lo == b_hi) {
        // whole block is one graph: block-reduce then 64 atomics
        float p = 0.f;
#pragma unroll
        for (int i = 0; i < 8; i++) p += fmaxf(acc[i], 0.f);
        red[grp * 64 + f] = p;
        __syncthreads();
        if (grp == 0) {
            float s = red[f] + red[64 + f] + red[128 + f] + red[192 + f];
            atomicAdd(&g_pool[b_lo * 64 + f], s);
        }
    } else {
        // boundary block (rare): per-node atomics
#pragma unroll
        for (int i = 0; i < 8; i++) {
            int node = nbase + grp * 8 + i;
            atomicAdd(&g_pool[__ldg(&batch[node]) * 64 + f], fmaxf(acc[i], 0.f));
        }
    }
}

// ---------------- out[g] = (sum_f pool[g][f]*Wr[f]) / count + br ----------------
__global__ void k_final(const float* __restrict__ Wr, const float* __restrict__ br,
                        float* __restrict__ out) {
    int g = threadIdx.x;
    if (g >= NG) return;
    float s = 0.f;
#pragma unroll
    for (int f = 0; f < 64; f++) s += g_pool[g * 64 + f] * Wr[f];
    out[g] = s / fmaxf((float)g_gcnt[g], 1.f) + br[0];
}

extern "C" void kernel_launch(void* const* d_in, const int* in_sizes, int n_in,
                              void* d_out, int out_size) {
    const float* x     = (const float*)d_in[0];
    const int*   ei    = (const int*)d_in[1];     // int32
    const int*   batch = (const int*)d_in[2];     // int32
    const float* W1    = (const float*)d_in[3];
    const float* b1    = (const float*)d_in[4];
    const float* W2    = (const float*)d_in[5];
    const float* b2    = (const float*)d_in[6];
    const float* Wr    = (const float*)d_in[7];
    const float* br    = (const float*)d_in[8];
    float*       out   = (float*)d_out;

    (void)in_sizes; (void)n_in; (void)out_size;

    const int nb = (NN + 1023) / 1024;  // 98 scan blocks

    k_zero<<<(NN + 255) / 256, 256>>>();
    k_hist<<<4096, 256>>>(ei);
    k_dinv<<<(NN + 255) / 256, 256>>>();
    k_gcnt<<<(NN + 255) / 256, 256>>>(batch);
    k_scanA<<<nb, 1024>>>();
    k_scanB<<<1, 32>>>(nb);
    k_scanC<<<(NN + 255) / 256, 256>>>();
    k_fill<<<4096, 256>>>(ei);

    k_conv3<<<(NN + 7) / 8, 256>>>(x);                    // c3 = conv(x)
    k_h<<<(NN * 32 + 255) / 256, 256>>>(W1, b1);          // h = relu(c3@W1+b1) fp16
    k_conv64<<<(NN + 7) / 8, 256>>>();                    // C = conv(h)
    k_g2p<<<NN / 32, 256>>>(W2, b2, batch);               // pool(relu(C@W2+b2))

    k_final<<<1, 64>>>(Wr, br, out);
}

// round 14
// speedup vs baseline: 1.6062x; 1.2546x over previous
#include <cuda_runtime.h>
#include <cuda_fp16.h>

#define NN 100000
#define NE 3200000
#define NG 64
#define F  64

// ---- scratch (static device globals; no dynamic allocation) ----
__device__ int    g_cnt[NN];          // in-degree (real edges) per dst
__device__ int    g_cur[NN];          // fill cursor per dst
__device__ int    g_rowptr[NN];       // CSR row start (exclusive scan of g_cnt)
__device__ int    g_bsum[128];        // block sums for scan
__device__ float  g_dinv[NN];         // deg^-1/2 (with self loop)
__device__ int2   g_edge[NE];         // CSR: {src, w_bits} packed, grouped by dst
__device__ float  g_c3[(size_t)NN * 3];     // conv(x)  [N,3]
__device__ __half2 g_h[(size_t)NN * 32];    // h = relu(conv(x)@W1+b1)  fp16 [N,64]
__device__ float  g_C[(size_t)NN * F];      // conv(h)  [N,64] fp32
__device__ float  g_pool[NG * F];
__device__ int    g_gcnt[NG];

// ---------------- init ----------------
__global__ void k_zero() {
    int i = blockIdx.x * blockDim.x + threadIdx.x;
    if (i < NN) { g_cnt[i] = 0; g_cur[i] = 0; }
    if (i < NG * F) g_pool[i] = 0.f;
    if (i < NG) g_gcnt[i] = 0;
}

// ---------------- degree histogram over dst ----------------
__global__ void k_hist(const int* __restrict__ ei) {
    int stride = gridDim.x * blockDim.x;
    for (int e = blockIdx.x * blockDim.x + threadIdx.x; e < NE; e += stride)
        atomicAdd(&g_cnt[ei[NE + e]], 1);
}

// ---------------- per-graph node counts, warp-aggregated ----------------
__global__ void k_gcnt(const int* __restrict__ batch) {
    int i = blockIdx.x * blockDim.x + threadIdx.x;
    if (i >= NN) return;
    int b = batch[i];
    unsigned m = __match_any_sync(__activemask(), b);
    int leader = __ffs(m) - 1;
    if ((threadIdx.x & 31) == leader)
        atomicAdd(&g_gcnt[b], __popc(m));
}

// ---------------- exclusive scan of g_cnt -> g_rowptr (warp-shuffle) ----------------
__global__ void k_scanA() {
    __shared__ int wsum[32];
    int i = blockIdx.x * 1024 + threadIdx.x;
    int lane = threadIdx.x & 31, warp = threadIdx.x >> 5;
    int v = (i < NN) ? g_cnt[i] : 0;
    int s = v;
#pragma unroll
    for (int off = 1; off < 32; off <<= 1) {
        int t = __shfl_up_sync(0xffffffffu, s, off);
        if (lane >= off) s += t;
    }
    if (lane == 31) wsum[warp] = s;
    __syncthreads();
    if (warp == 0) {
        int w = wsum[lane];
        int ws = w;
#pragma unroll
        for (int off = 1; off < 32; off <<= 1) {
            int t = __shfl_up_sync(0xffffffffu, ws, off);
            if (lane >= off) ws += t;
        }
        wsum[lane] = ws - w;   // exclusive warp offsets
        if (lane == 31) g_bsum[blockIdx.x] = ws;  // block total
    }
    __syncthreads();
    if (i < NN) g_rowptr[i] = s - v + wsum[warp];
}

__global__ void k_scanB(int nb) {
    if (threadIdx.x == 0) {
        int run = 0;
        for (int i = 0; i < nb; i++) { int t = g_bsum[i]; g_bsum[i] = run; run += t; }
    }
}

// fold dinv computation in here (one pass over g_cnt anyway)
__global__ void k_scanC() {
    int i = blockIdx.x * blockDim.x + threadIdx.x;
    if (i < NN) {
        g_rowptr[i] += g_bsum[i >> 10];
        g_dinv[i] = rsqrtf((float)(g_cnt[i] + 1));  // +1 self loop
    }
}

// ---------------- CSR fill: packed {src, weight} ----------------
__global__ void k_fill(const int* __restrict__ ei) {
    int stride = gridDim.x * blockDim.x;
    for (int e = blockIdx.x * blockDim.x + threadIdx.x; e < NE; e += stride) {
        int s = ei[e];
        int d = ei[NE + e];
        float w = g_dinv[s] * g_dinv[d];
        int pos = g_rowptr[d] + atomicAdd(&g_cur[d], 1);
        g_edge[pos] = make_int2(s, __float_as_int(w));
    }
}

// ---------------- conv3: g_c3 = conv(x), warp per node, lanes over edges ----------------
__global__ void k_conv3(const float* __restrict__ x) {
    int n = blockIdx.x * 8 + (threadIdx.x >> 5);
    int lane = threadIdx.x & 31;
    if (n >= NN) return;
    int r0 = g_rowptr[n];
    int r1 = r0 + g_cnt[n];
    float a0 = 0.f, a1 = 0.f, a2 = 0.f;
    for (int i = r0 + lane; i < r1; i += 32) {
        int2 e = __ldg(&g_edge[i]);
        float w = __int_as_float(e.y);
        int s = e.x;
        a0 += w * __ldg(&x[s * 3]);
        a1 += w * __ldg(&x[s * 3 + 1]);
        a2 += w * __ldg(&x[s * 3 + 2]);
    }
#pragma unroll
    for (int off = 16; off > 0; off >>= 1) {
        a0 += __shfl_down_sync(0xffffffffu, a0, off);
        a1 += __shfl_down_sync(0xffffffffu, a1, off);
        a2 += __shfl_down_sync(0xffffffffu, a2, off);
    }
    if (lane == 0) {
        float dn = g_dinv[n], sw = dn * dn;
        g_c3[n * 3]     = a0 + sw * __ldg(&x[n * 3]);
        g_c3[n * 3 + 1] = a1 + sw * __ldg(&x[n * 3 + 1]);
        g_c3[n * 3 + 2] = a2 + sw * __ldg(&x[n * 3 + 2]);
    }
}

// ---------------- h = relu(c3 @ W1 + b1), fp16 out ----------------
__global__ void k_h(const float* __restrict__ W1, const float* __restrict__ b1) {
    int idx = blockIdx.x * blockDim.x + threadIdx.x;
    if (idx >= NN * 32) return;
    int n = idx >> 5, t = idx & 31;
    int f0 = t * 2;
    float c0 = __ldg(&g_c3[n * 3]), c1 = __ldg(&g_c3[n * 3 + 1]), c2 = __ldg(&g_c3[n * 3 + 2]);
    float v0 = __ldg(&b1[f0])     + c0 * __ldg(&W1[f0])     + c1 * __ldg(&W1[64 + f0])     + c2 * __ldg(&W1[128 + f0]);
    float v1 = __ldg(&b1[f0 + 1]) + c0 * __ldg(&W1[f0 + 1]) + c1 * __ldg(&W1[64 + f0 + 1]) + c2 * __ldg(&W1[128 + f0 + 1]);
    v0 = fmaxf(v0, 0.f);
    v1 = fmaxf(v1, 0.f);
    g_h[(size_t)n * 32 + t] = __floats2half2_rn(v0, v1);
}

// ---------------- conv64: g_C = conv(h), warp per node (fp16 gather) ----------------
__global__ void k_conv64() {
    int n = blockIdx.x * 8 + (threadIdx.x >> 5);
    int lane = threadIdx.x & 31;
    if (n >= NN) return;
    int r0 = g_rowptr[n];
    int r1 = r0 + g_cnt[n];
    float ax = 0.f, ay = 0.f;
#pragma unroll 4
    for (int i = r0; i < r1; i++) {
        int2 e = __ldg(&g_edge[i]);          // broadcast 8B
        float w = __int_as_float(e.y);
        float2 v = __half22float2(__ldg(&g_h[(size_t)e.x * 32 + lane]));  // 128B row
        ax += w * v.x;
        ay += w * v.y;
    }
    float dn = g_dinv[n], sw = dn * dn;
    float2 v = __half22float2(__ldg(&g_h[(size_t)n * 32 + lane]));
    ax += sw * v.x;
    ay += sw * v.y;
    ((float2*)g_C)[(size_t)n * 32 + lane] = make_float2(ax, ay);
}

// ---------------- h2 = relu(g_C @ W2 + b2), fused pooling ----------------
__global__ void k_g2p(const float* __restrict__ W2, const float* __restrict__ b2,
                      const int* __restrict__ batch) {
    __shared__ float W2s[64 * 64];          // [k*64 + f]
    __shared__ float hs[32 * 68];           // 32 node rows, padded
    __shared__ float red[4 * 64];           // grp partial sums per feature
    int tid = threadIdx.x;
    int nbase = blockIdx.x * 32;
    for (int i = tid; i < 4096; i += 256) W2s[i] = W2[i];
    for (int i = tid; i < 2048; i += 256) {
        int node = i >> 6, k = i & 63;
        hs[node * 68 + k] = g_C[(size_t)(nbase + node) * 64 + k];
    }
    __syncthreads();
    int f = tid & 63, grp = tid >> 6;       // grp owns 8 nodes
    float bf = __ldg(&b2[f]);
    float acc[8];
#pragma unroll
    for (int i = 0; i < 8; i++) acc[i] = bf;
#pragma unroll 4
    for (int k4 = 0; k4 < 64; k4 += 4) {
        float4 hv[8];
#pragma unroll
        for (int i = 0; i < 8; i++)
            hv[i] = *(const float4*)&hs[(grp * 8 + i) * 68 + k4];
#pragma unroll
        for (int j = 0; j < 4; j++) {
            float wk = W2s[(k4 + j) * 64 + f];
#pragma unroll
            for (int i = 0; i < 8; i++) {
                float h = (j == 0) ? hv[i].x : (j == 1) ? hv[i].y : (j == 2) ? hv[i].z : hv[i].w;
                acc[i] += h * wk;
            }
        }
    }
    int b_lo = __ldg(&batch[nbase]);
    int b_hi = __ldg(&batch[nbase + 31]);
    if (b_lo == b_hi) {
        // whole block is one graph: block-reduce then 64 atomics
        float p = 0.f;
#pragma unroll
        for (int i = 0; i < 8; i++) p += fmaxf(acc[i], 0.f);
        red[grp * 64 + f] = p;
        __syncthreads();
        if (grp == 0) {
            float s = red[f] + red[64 + f] + red[128 + f] + red[192 + f];
            atomicAdd(&g_pool[b_lo * 64 + f], s);
        }
    } else {
        // boundary block (rare): per-node atomics
#pragma unroll
        for (int i = 0; i < 8; i++) {
            int node = nbase + grp * 8 + i;
            atomicAdd(&g_pool[__ldg(&batch[node]) * 64 + f], fmaxf(acc[i], 0.f));
        }
    }
}

// ---------------- out[g] = (sum_f pool[g][f]*Wr[f]) / count + br ----------------
__global__ void k_final(const float* __restrict__ Wr, const float* __restrict__ br,
                        float* __restrict__ out) {
    int g = threadIdx.x;
    if (g >= NG) return;
    float s = 0.f;
#pragma unroll
    for (int f = 0; f < 64; f++) s += g_pool[g * 64 + f] * Wr[f];
    out[g] = s / fmaxf((float)g_gcnt[g], 1.f) + br[0];
}

extern "C" void kernel_launch(void* const* d_in, const int* in_sizes, int n_in,
                              void* d_out, int out_size) {
    const float* x     = (const float*)d_in[0];
    const int*   ei    = (const int*)d_in[1];     // int32
    const int*   batch = (const int*)d_in[2];     // int32
    const float* W1    = (const float*)d_in[3];
    const float* b1    = (const float*)d_in[4];
    const float* W2    = (const float*)d_in[5];
    const float* b2    = (const float*)d_in[6];
    const float* Wr    = (const float*)d_in[7];
    const float* br    = (const float*)d_in[8];
    float*       out   = (float*)d_out;

    (void)in_sizes; (void)n_in; (void)out_size;

    const int nb = (NN + 1023) / 1024;  // 98 scan blocks

    k_zero<<<(NN + 255) / 256, 256>>>();
    k_hist<<<4096, 256>>>(ei);
    k_gcnt<<<(NN + 255) / 256, 256>>>(batch);
    k_scanA<<<nb, 1024>>>();
    k_scanB<<<1, 32>>>(nb);
    k_scanC<<<(NN + 255) / 256, 256>>>();     // rowptr offsets + dinv
    k_fill<<<4096, 256>>>(ei);

    k_conv3<<<(NN + 7) / 8, 256>>>(x);                    // c3 = conv(x)
    k_h<<<(NN * 32 + 255) / 256, 256>>>(W1, b1);          // h = relu(c3@W1+b1) fp16
    k_conv64<<<(NN + 7) / 8, 256>>>();                    // C = conv(h)
    k_g2p<<<NN / 32, 256>>>(W2, b2, batch);               // pool(relu(C@W2+b2))

    k_final<<<1, 64>>>(Wr, br, out);
}